// round 4
// baseline (speedup 1.0000x reference)
#include <cuda_runtime.h>
#include <cuda_bf16.h>
#include <math.h>

// Problem dims (fixed by the dataset)
#define NB 4
#define CH 3
#define HH 1080
#define WW 1920
#define HW (HH * WW)
#define NHW (NB * HW)

#define SZ_IN     (NB * 3 * HW)   // 24883200
#define SZ_FLOW   (NB * 2 * HW)   // 16588800
#define SZ_METRIC (NB * 1 * HW)   //  8294400

// Accumulator: [N, H, W, 4] interleaved (c0*m*w, c1*m*w, c2*m*w, m*w sums)
// 4 * 1080 * 1920 * 4 floats = 132.7 MB, zero-initialized scratch.
__device__ float g_acc[(size_t)NHW * 4];

__global__ void zero_kernel() {
    int i = blockIdx.x * blockDim.x + threadIdx.x;
    if (i < NHW) {
        float4 z = make_float4(0.f, 0.f, 0.f, 0.f);
        reinterpret_cast<float4*>(g_acc)[i] = z;
    }
}

__global__ void splat_kernel(const float* __restrict__ in,
                             const float* __restrict__ flow,
                             const float* __restrict__ metric) {
    int p = blockIdx.x * blockDim.x + threadIdx.x;
    if (p >= NHW) return;
    int b   = p / HW;
    int rem = p - b * HW;
    int y   = rem / WW;
    int x   = rem - y * WW;

    float fx = flow[(size_t)(b * 2 + 0) * HW + rem];
    float fy = flow[(size_t)(b * 2 + 1) * HW + rem];
    float tx = (float)x + fx;
    float ty = (float)y + fy;
    if (!isfinite(tx) || !isfinite(ty)) return;  // ref zeroes these contributions

    float m  = __expf(metric[p]);
    float v0 = in[(size_t)(b * 3 + 0) * HW + rem] * m;
    float v1 = in[(size_t)(b * 3 + 1) * HW + rem] * m;
    float v2 = in[(size_t)(b * 3 + 2) * HW + rem] * m;

    float fxf = floorf(tx);
    float fyf = floorf(ty);
    int x0 = (int)fxf;
    int y0 = (int)fyf;
    float ax = tx - fxf;   // frac in [0,1)
    float ay = ty - fyf;

    float wx[2] = {1.f - ax, ax};
    float wy[2] = {1.f - ay, ay};

    float* base = g_acc + (size_t)b * HW * 4;

#pragma unroll
    for (int dy = 0; dy < 2; dy++) {
        int iy = y0 + dy;
        if (iy < 0 || iy >= HH) continue;
#pragma unroll
        for (int dx = 0; dx < 2; dx++) {
            int ix = x0 + dx;
            if (ix < 0 || ix >= WW) continue;
            float w = wx[dx] * wy[dy];
            float* ptr = base + ((size_t)iy * WW + ix) * 4;
            // Vector reduction: one 16B RED per corner. The 4th lane is the
            // reference's splatted exp(metric) channel: accumulate m*w (NOT w).
            asm volatile(
                "red.global.add.v4.f32 [%0], {%1, %2, %3, %4};"
                :: "l"(ptr), "f"(v0 * w), "f"(v1 * w), "f"(v2 * w), "f"(m * w)
                : "memory");
        }
    }
}

__global__ void norm_kernel(float* __restrict__ out) {
    int p = blockIdx.x * blockDim.x + threadIdx.x;
    if (p >= NHW) return;
    int b   = p / HW;
    int rem = p - b * HW;
    float4 a = reinterpret_cast<const float4*>(g_acc)[p];
    float inv = 1.0f / (a.w + 1e-7f);
    out[(size_t)(b * 3 + 0) * HW + rem] = a.x * inv;
    out[(size_t)(b * 3 + 1) * HW + rem] = a.y * inv;
    out[(size_t)(b * 3 + 2) * HW + rem] = a.z * inv;
}

extern "C" void kernel_launch(void* const* d_in, const int* in_sizes, int n_in,
                              void* d_out, int out_size) {
    // Identify inputs by element count — robust to any metadata ordering.
    const float* tenIn     = nullptr;
    const float* tenFlow   = nullptr;
    const float* tenMetric = nullptr;
    for (int i = 0; i < n_in; i++) {
        if      (in_sizes[i] == SZ_IN)     tenIn     = (const float*)d_in[i];
        else if (in_sizes[i] == SZ_FLOW)   tenFlow   = (const float*)d_in[i];
        else if (in_sizes[i] == SZ_METRIC) tenMetric = (const float*)d_in[i];
    }
    float* out = (float*)d_out;

    const int threads = 256;
    const int blocks  = (NHW + threads - 1) / threads;  // 32400

    zero_kernel<<<blocks, threads>>>();
    splat_kernel<<<blocks, threads>>>(tenIn, tenFlow, tenMetric);
    norm_kernel<<<blocks, threads>>>(out);
}